// round 16
// baseline (speedup 1.0000x reference)
#include <cuda_runtime.h>
#include <cuda_fp16.h>
#include <cstdint>

// Problem constants
#define B_N 65536
#define D_N 256
#define K_N 4096
#define DECAYF 0.99f
#define OMDECAYF 0.01f
#define EPSF 1e-5f
#define TAU 0.25f

// Output layout (concatenated float32, tuple order)
#define OFF_IDX  0
#define OFF_Q    65536
#define OFF_NS   16842752
#define OFF_LOSS 16842753
#define OFF_CS   16842754
#define OFF_E    16846850

// ---------------- device scratch ----------------
__device__ float  g_sumT[K_N * D_N];     // [K,D] scatter-add of x
__device__ float  g_embedT[K_N * D_N];   // [K,D] fp32 codebook
__device__ __half g_ebh[K_N * D_N];      // [K,D] fp16 codebook (GEMM B)
__device__ float  g_counts[K_N];
__device__ float  g_enorm[K_N];
__device__ int    g_idx[B_N];
__device__ int    g_fall[B_N];
__device__ int    g_nfall;
__device__ float  g_scalars[4];          // 0: loss_sum, 1: n_sum, 2: n_small

// ---------------- zero scratch ---------------------------------------------
__global__ void k_prep() {
    int i = blockIdx.x * blockDim.x + threadIdx.x;
    if (i < K_N * D_N / 4)
        reinterpret_cast<float4*>(g_sumT)[i] = make_float4(0.f, 0.f, 0.f, 0.f);
    if (i < K_N) g_counts[i] = 0.0f;
    if (i < 4) g_scalars[i] = 0.0f;
    if (i == 0) g_nfall = 0;
}

// ---------------- transpose embed [D,K] -> [K,D] (f32 + fp16) --------------
__global__ void k_transp(const float* __restrict__ embed) {
    __shared__ float t[32][33];
    int bx = blockIdx.x, by = blockIdx.y;
    int kx = bx * 32 + threadIdx.x;
    int dy = by * 32 + threadIdx.y;
    #pragma unroll
    for (int i = 0; i < 32; i += 8)
        t[threadIdx.y + i][threadIdx.x] = embed[(dy + i) * K_N + kx];
    __syncthreads();
    int k2 = bx * 32 + threadIdx.y;
    int d2 = by * 32 + threadIdx.x;
    #pragma unroll
    for (int i = 0; i < 32; i += 8) {
        float v = t[threadIdx.x][threadIdx.y + i];
        g_embedT[(k2 + i) * D_N + d2] = v;
        g_ebh[(k2 + i) * D_N + d2] = __float2half_rn(v);
    }
}

// ---------------- ||e_k||^2 (exact fp32, sequential-d order) ---------------
__global__ void k_enorm(const float* __restrict__ embed) {
    int k = blockIdx.x * blockDim.x + threadIdx.x;
    if (k >= K_N) return;
    float acc = 0.0f;
    #pragma unroll 16
    for (int d = 0; d < D_N; d++) {
        float v = embed[d * K_N + k];
        acc = fmaf(v, v, acc);
    }
    g_enorm[k] = acc;
}

// ---------------- mma / ldmatrix / cp.async helpers ------------------------
__device__ __forceinline__ void mma_f16(float* c, const unsigned* a, const unsigned* b) {
    asm volatile(
        "mma.sync.aligned.m16n8k16.row.col.f32.f16.f16.f32 "
        "{%0,%1,%2,%3}, {%4,%5,%6,%7}, {%8,%9}, {%0,%1,%2,%3};\n"
        : "+f"(c[0]), "+f"(c[1]), "+f"(c[2]), "+f"(c[3])
        : "r"(a[0]), "r"(a[1]), "r"(a[2]), "r"(a[3]), "r"(b[0]), "r"(b[1]));
}
#define LDSM_X4(r0, r1, r2, r3, addr) \
    asm volatile("ldmatrix.sync.aligned.m8n8.x4.shared.b16 {%0,%1,%2,%3}, [%4];" \
        : "=r"(r0), "=r"(r1), "=r"(r2), "=r"(r3) : "r"(addr))
__device__ __forceinline__ void cp16(unsigned dst, const void* src) {
    asm volatile("cp.async.ca.shared.global [%0], [%1], 16;\n" :: "r"(dst), "l"(src));
}
__device__ __forceinline__ void cp_commit() { asm volatile("cp.async.commit_group;\n"); }
template <int N>
__device__ __forceinline__ void cp_wait() {
    asm volatile("cp.async.wait_group %0;\n" :: "n"(N));
}
__device__ __forceinline__ void red_add_v4(float* addr, float4 v) {
    asm volatile("red.global.v4.f32.add [%0], {%1, %2, %3, %4};"
                 :: "l"(addr), "f"(v.x), "f"(v.y), "f"(v.z), "f"(v.w) : "memory");
}

// ---------------- fused fp16 GEMM + certification + quantize ---------------
// score(i,k) = ||e_k||^2 - 2 * x_i . e_k  (fp16 inputs, fp32 accumulate)
// Certified rows (fp16 top-2 gap > TAU) are fully finished here: idx, Q/STE,
// loss, histogram, scatter-add. Uncertified rows go to the exact fallback,
// which completes them end-to-end.
#define GBM 128
#define GBN 128
#define AROWB 528               // (256 + 8 pad) halfs = 528 bytes per row
#define ABYTES (GBM * AROWB)    // 67584
#define BBYTES (GBN * AROWB)    // 67584
#define SMEM_GEMM (ABYTES + 2 * BBYTES)   // 202752
#define NT (K_N / GBN)          // 32

__global__ __launch_bounds__(512, 1)
void k_gemm_top2(const float* __restrict__ x, const __half* __restrict__ ebh,
                 float* __restrict__ out) {
    extern __shared__ __align__(16) unsigned char raw[];
    __shared__ float sEn[K_N];            // full enorm table, written once
    __shared__ float sS1[GBM][4], sS2[GBM][4];
    __shared__ int   sK1[GBM][4], sK2[GBM][4];
    __shared__ int   sIdx[GBM];
    __shared__ int   sFlag[GBM];
    __shared__ float blk_loss;

    const int tid = threadIdx.x;
    const int m0 = blockIdx.x * GBM;
    const int warp = tid >> 5, lane = tid & 31;
    const int wm = warp >> 2, wn = warp & 3;   // 4x4 warp grid, warp tile 32x32
    const int g = lane >> 2, q = lane & 3;

    const unsigned sA = (unsigned)__cvta_generic_to_shared(raw);
    const unsigned sB0 = sA + ABYTES;

    if (tid == 0) blk_loss = 0.0f;
    for (int i = tid; i < K_N; i += 512) sEn[i] = g_enorm[i];

    const unsigned a_lane_off = (unsigned)((lane & 15) * AROWB + ((lane >> 4) << 4));
    const unsigned b_lane_off =
        (unsigned)(((lane & 7) + ((lane & 16) >> 1)) * AROWB + ((lane & 8) << 1));

    // ---- load A: fp32 x -> fp16 smem, once (LDG + convert + STS) ----
    #pragma unroll
    for (int i = tid; i < GBM * 64; i += 512) {       // 64 float4 per row
        int r = i >> 6, c4 = i & 63;
        float4 v = reinterpret_cast<const float4*>(x + (m0 + r) * D_N)[c4];
        __half2* dst = reinterpret_cast<__half2*>(raw + r * AROWB + c4 * 8);
        dst[0] = __floats2half2_rn(v.x, v.y);
        dst[1] = __floats2half2_rn(v.z, v.w);
    }
    // ---- load B tile 0 (cp.async) ----
    #pragma unroll
    for (int i = tid; i < GBN * 32; i += 512) {
        int r = i >> 5, c8 = i & 31;
        cp16(sB0 + r * AROWB + c8 * 16, ebh + r * D_N + c8 * 8);
    }
    cp_commit();

    float t1s[4], t2s[4];
    unsigned pk[4];
    #pragma unroll
    for (int i = 0; i < 4; i++) { t1s[i] = 3.4e38f; t2s[i] = 3.4e38f; pk[i] = 0; }

    for (int t = 0; t < NT; t++) {
        const unsigned bb = sB0 + (t & 1) * BBYTES;
        if (t + 1 < NT) {
            const __half* src = ebh + (t + 1) * GBN * D_N;
            unsigned nb = sB0 + ((t + 1) & 1) * BBYTES;
            #pragma unroll
            for (int i = tid; i < GBN * 32; i += 512) {
                int r = i >> 5, c8 = i & 31;
                cp16(nb + r * AROWB + c8 * 16, src + r * D_N + c8 * 8);
            }
            cp_commit();
            cp_wait<1>();
        } else {
            cp_wait<0>();
        }
        __syncthreads();

        float acc[2][4][4];
        #pragma unroll
        for (int a = 0; a < 2; a++)
            #pragma unroll
            for (int b = 0; b < 4; b++)
                #pragma unroll
                for (int c = 0; c < 4; c++) acc[a][b][c] = 0.0f;

        #pragma unroll
        for (int k0 = 0; k0 < D_N; k0 += 16) {
            unsigned a[2][4], b[2][4];
            #pragma unroll
            for (int mf = 0; mf < 2; mf++) {
                unsigned addr = sA + (wm * 32 + mf * 16) * AROWB + a_lane_off + k0 * 2;
                LDSM_X4(a[mf][0], a[mf][1], a[mf][2], a[mf][3], addr);
            }
            #pragma unroll
            for (int pr = 0; pr < 2; pr++) {
                unsigned addr = bb + (wn * 32 + pr * 16) * AROWB + b_lane_off + k0 * 2;
                LDSM_X4(b[pr][0], b[pr][1], b[pr][2], b[pr][3], addr);
            }
            #pragma unroll
            for (int mf = 0; mf < 2; mf++)
                #pragma unroll
                for (int nf = 0; nf < 4; nf++)
                    mma_f16(acc[mf][nf], a[mf], &b[nf >> 1][(nf & 1) * 2]);
        }
        __syncthreads();

        const int n0 = t * GBN;
        #pragma unroll
        for (int nf = 0; nf < 4; nf++) {
            #pragma unroll
            for (int e = 0; e < 2; e++) {
                int col = wn * 32 + nf * 8 + 2 * q + e;
                int k = n0 + col;
                float en = sEn[k];
                #pragma unroll
                for (int mf = 0; mf < 2; mf++) {
                    #pragma unroll
                    for (int h = 0; h < 2; h++) {
                        float s = fmaf(-2.0f, acc[mf][nf][h * 2 + e], en);
                        int rid = mf * 2 + h;
                        if (s < t1s[rid]) {
                            t2s[rid] = t1s[rid];
                            t1s[rid] = s;
                            pk[rid] = ((pk[rid] & 0xffffu) << 16) | (unsigned)k;
                        } else if (s < t2s[rid]) {
                            t2s[rid] = s;
                            pk[rid] = (pk[rid] & 0xffffu) | ((unsigned)k << 16);
                        }
                    }
                }
            }
        }
    }

    // ---- in-warp merge of top-2 across the 4 q-lanes sharing each row ----
    #pragma unroll
    for (int rid = 0; rid < 4; rid++) {
        #pragma unroll
        for (int off = 1; off <= 2; off <<= 1) {
            float o1 = __shfl_xor_sync(0xffffffffu, t1s[rid], off);
            float o2 = __shfl_xor_sync(0xffffffffu, t2s[rid], off);
            unsigned op = __shfl_xor_sync(0xffffffffu, pk[rid], off);
            int ok1 = (int)(op & 0xffffu), ok2 = (int)(op >> 16);
            float s1 = t1s[rid], s2 = t2s[rid];
            int k1 = (int)(pk[rid] & 0xffffu), k2 = (int)(pk[rid] >> 16);
            float n1, n2; int nk1, nk2;
            bool ob = (o1 < s1) || (o1 == s1 && ok1 < k1);
            if (ob) {
                n1 = o1; nk1 = ok1;
                bool tb = (s1 < o2) || (s1 == o2 && k1 < ok2);
                if (tb) { n2 = s1; nk2 = k1; } else { n2 = o2; nk2 = ok2; }
            } else {
                n1 = s1; nk1 = k1;
                bool tb = (o1 < s2) || (o1 == s2 && ok1 < k2);
                if (tb) { n2 = o1; nk2 = ok1; } else { n2 = s2; nk2 = k2; }
            }
            t1s[rid] = n1; t2s[rid] = n2;
            pk[rid] = (unsigned)nk1 | ((unsigned)nk2 << 16);
        }
    }
    if (q == 0) {
        #pragma unroll
        for (int rid = 0; rid < 4; rid++) {
            int mf = rid >> 1, h = rid & 1;
            int rl = wm * 32 + mf * 16 + h * 8 + g;
            sS1[rl][wn] = t1s[rid]; sK1[rl][wn] = (int)(pk[rid] & 0xffffu);
            sS2[rl][wn] = t2s[rid]; sK2[rl][wn] = (int)(pk[rid] >> 16);
        }
    }
    __syncthreads();
    // ---- final cross-warp merge + certification ----
    if (tid < GBM) {
        float b1 = 3.4e38f, b2 = 3.4e38f; int bk = 1 << 30;
        #pragma unroll
        for (int w = 0; w < 4; w++) {
            float s1 = sS1[tid][w]; int kk1 = sK1[tid][w];
            float s2 = sS2[tid][w]; int kk2 = sK2[tid][w];
            if (s1 < b1 || (s1 == b1 && kk1 < bk)) { b2 = b1; b1 = s1; bk = kk1; }
            else if (s1 < b2) b2 = s1;
            if (s2 < b1 || (s2 == b1 && kk2 < bk)) { b2 = b1; b1 = s2; bk = kk2; }
            else if (s2 < b2) b2 = s2;
        }
        int row = m0 + tid;
        g_idx[row] = bk;
        sIdx[tid] = bk;
        int flag = (b2 - b1 < TAU) ? 1 : 0;
        sFlag[tid] = flag;
        if (flag) {
            int pos = atomicAdd(&g_nfall, 1);
            g_fall[pos] = row;
        }
    }
    __syncthreads();

    // ---- fused quantize/STE/loss/scatter for certified rows ----
    float lacc = 0.0f;
    for (int r = warp; r < GBM; r += 16) {
        if (sFlag[r]) continue;
        int k = sIdx[r];
        int row = m0 + r;
        const float4* xr = reinterpret_cast<const float4*>(x + row * D_N);
        const float4* er = reinterpret_cast<const float4*>(g_embedT + k * D_N);
        int c0 = lane * 2, c1 = lane * 2 + 1;
        float4 xv0 = xr[c0], xv1 = xr[c1];
        float4 ev0 = er[c0], ev1 = er[c1];
        float4* outr = reinterpret_cast<float4*>(out + OFF_Q + row * D_N);
        float d0 = ev0.x - xv0.x, d1 = ev0.y - xv0.y, d2 = ev0.z - xv0.z, d3 = ev0.w - xv0.w;
        outr[c0] = make_float4(xv0.x + d0, xv0.y + d1, xv0.z + d2, xv0.w + d3);
        lacc = fmaf(d0, d0, lacc); lacc = fmaf(d1, d1, lacc);
        lacc = fmaf(d2, d2, lacc); lacc = fmaf(d3, d3, lacc);
        red_add_v4(&g_sumT[k * D_N + c0 * 4], xv0);
        float e0 = ev1.x - xv1.x, e1 = ev1.y - xv1.y, e2 = ev1.z - xv1.z, e3 = ev1.w - xv1.w;
        outr[c1] = make_float4(xv1.x + e0, xv1.y + e1, xv1.z + e2, xv1.w + e3);
        lacc = fmaf(e0, e0, lacc); lacc = fmaf(e1, e1, lacc);
        lacc = fmaf(e2, e2, lacc); lacc = fmaf(e3, e3, lacc);
        red_add_v4(&g_sumT[k * D_N + c1 * 4], xv1);
        if (lane == 0) {
            atomicAdd(&g_counts[k], 1.0f);
            out[OFF_IDX + row] = (float)k;
        }
    }
    #pragma unroll
    for (int o = 16; o > 0; o >>= 1) lacc += __shfl_down_sync(0xffffffffu, lacc, o);
    if (lane == 0) atomicAdd(&blk_loss, lacc);
    __syncthreads();
    if (tid == 0) atomicAdd(&g_scalars[0], blk_loss);
}

// ---------------- exact full scan + quantize for flagged rows --------------
__global__ __launch_bounds__(256)
void k_fallback(const float* __restrict__ x, const float* __restrict__ embed,
                float* __restrict__ out) {
    __shared__ float xs[D_N];
    __shared__ float rS[8];
    __shared__ int   rK[8];
    __shared__ int   sK;
    int tid = threadIdx.x, lane = tid & 31, warp = tid >> 5;
    int n = g_nfall;
    for (int w = blockIdx.x; w < n; w += gridDim.x) {
        int row = g_fall[w];
        __syncthreads();
        xs[tid] = x[row * D_N + tid];
        __syncthreads();

        float acc[16];
        #pragma unroll
        for (int j = 0; j < 16; j++) acc[j] = 0.0f;
        for (int d = 0; d < D_N; d++) {
            float xd = xs[d];
            const float* er = embed + d * K_N + tid;
            #pragma unroll
            for (int j = 0; j < 16; j++)
                acc[j] = fmaf(xd, er[j * 256], acc[j]);
        }
        float bs = 3.4e38f; int bk = 1 << 30;
        #pragma unroll
        for (int j = 0; j < 16; j++) {
            int k = tid + j * 256;
            float s = fmaf(-2.0f, acc[j], g_enorm[k]);
            if (s < bs || (s == bs && k < bk)) { bs = s; bk = k; }
        }
        #pragma unroll
        for (int o = 16; o > 0; o >>= 1) {
            float os = __shfl_down_sync(0xffffffffu, bs, o);
            int   ok = __shfl_down_sync(0xffffffffu, bk, o);
            if (os < bs || (os == bs && ok < bk)) { bs = os; bk = ok; }
        }
        if (lane == 0) { rS[warp] = bs; rK[warp] = bk; }
        __syncthreads();
        if (tid == 0) {
            float fbs = rS[0]; int fbk = rK[0];
            #pragma unroll
            for (int t = 1; t < 8; t++) {
                if (rS[t] < fbs || (rS[t] == fbs && rK[t] < fbk)) {
                    fbs = rS[t]; fbk = rK[t];
                }
            }
            g_idx[row] = fbk;
            sK = fbk;
            out[OFF_IDX + row] = (float)fbk;
            atomicAdd(&g_counts[fbk], 1.0f);
        }
        __syncthreads();
        // quantize this row: one d per thread (x row already in smem)
        int k = sK;
        float xv = xs[tid];
        float ev = g_embedT[k * D_N + tid];
        float diff = ev - xv;
        out[OFF_Q + row * D_N + tid] = xv + diff;
        atomicAdd(&g_sumT[k * D_N + tid], xv);
        float l = diff * diff;
        #pragma unroll
        for (int o = 16; o > 0; o >>= 1) l += __shfl_down_sync(0xffffffffu, l, o);
        if (lane == 0) rS[warp] = l;
        __syncthreads();
        if (tid == 0) {
            float ls = 0.0f;
            #pragma unroll
            for (int t = 0; t < 8; t++) ls += rS[t];
            atomicAdd(&g_scalars[0], ls);
        }
    }
}

// ---------------- new_cluster_size + reductions ---------------------------
__global__ void k_stats(const float* __restrict__ cluster_size,
                        float* __restrict__ out) {
    __shared__ float sSum[256], sSmall[256];
    int tid = threadIdx.x;
    int k = blockIdx.x * 256 + tid;
    float ncs = fmaf(DECAYF, cluster_size[k], OMDECAYF * g_counts[k]);
    out[OFF_CS + k] = ncs;
    sSum[tid] = ncs;
    sSmall[tid] = (ncs < 1.0f) ? 1.0f : 0.0f;
    __syncthreads();
    for (int o = 128; o > 0; o >>= 1) {
        if (tid < o) { sSum[tid] += sSum[tid + o]; sSmall[tid] += sSmall[tid + o]; }
        __syncthreads();
    }
    if (tid == 0) {
        atomicAdd(&g_scalars[1], sSum[0]);
        atomicAdd(&g_scalars[2], sSmall[0]);
    }
}

// ---------------- finalize: new_embed + scalars ---------------------------
__global__ void k_final(const float* __restrict__ embed_avg,
                        float* __restrict__ out) {
    int i = blockIdx.x * blockDim.x + threadIdx.x;
    if (i == 0) {
        out[OFF_NS]   = g_scalars[2];
        out[OFF_LOSS] = g_scalars[0] * (1.0f / ((float)B_N * (float)D_N));
    }
    if (i < D_N * K_N) {
        int k = i & (K_N - 1);
        int d = i >> 12;
        float ncs = out[OFF_CS + k];
        float n = g_scalars[1];
        float cs = (ncs + EPSF) / (n + (float)K_N * EPSF) * n;
        float navg = fmaf(DECAYF, embed_avg[i], OMDECAYF * g_sumT[k * D_N + d]);
        out[OFF_E + i] = navg / cs;
    }
}

// ---------------- launch ---------------------------------------------------
extern "C" void kernel_launch(void* const* d_in, const int* in_sizes, int n_in,
                              void* d_out, int out_size) {
    const float* x            = (const float*)d_in[0];  // [B, D]
    const float* embed        = (const float*)d_in[1];  // [D, K]
    const float* cluster_size = (const float*)d_in[2];  // [K]
    const float* embed_avg    = (const float*)d_in[3];  // [D, K]
    float* out = (float*)d_out;
    (void)in_sizes; (void)n_in; (void)out_size;

    static int smem_set = 0;
    if (!smem_set) {
        cudaFuncSetAttribute(k_gemm_top2,
                             cudaFuncAttributeMaxDynamicSharedMemorySize, SMEM_GEMM);
        smem_set = 1;
    }

    __half* ebh; cudaGetSymbolAddress((void**)&ebh, g_ebh);

    k_prep<<<(K_N * D_N / 4 + 255) / 256, 256>>>();
    k_transp<<<dim3(K_N / 32, D_N / 32), dim3(32, 8)>>>(embed);
    k_enorm<<<K_N / 32, 32>>>(embed);
    k_gemm_top2<<<B_N / GBM, 512, SMEM_GEMM>>>(x, ebh, out);
    k_fallback<<<1024, 256>>>(x, embed, out);
    k_stats<<<K_N / 256, 256>>>(cluster_size, out);
    k_final<<<(D_N * K_N + 255) / 256, 256>>>(embed_avg, out);
}

// round 17
// speedup vs baseline: 1.1117x; 1.1117x over previous
#include <cuda_runtime.h>
#include <cuda_fp16.h>
#include <cstdint>

// Problem constants
#define B_N 65536
#define D_N 256
#define K_N 4096
#define DECAYF 0.99f
#define OMDECAYF 0.01f
#define EPSF 1e-5f
#define TAU 0.25f

// Output layout (concatenated float32, tuple order)
#define OFF_IDX  0
#define OFF_Q    65536
#define OFF_NS   16842752
#define OFF_LOSS 16842753
#define OFF_CS   16842754
#define OFF_E    16846850

// ---------------- device scratch ----------------
__device__ float  g_sumT[K_N * D_N];     // [K,D] scatter-add of x
__device__ float  g_embedT[K_N * D_N];   // [K,D] fp32 codebook
__device__ __half g_ebh[K_N * D_N];      // [K,D] fp16 codebook (GEMM B)
__device__ __half g_xh[B_N * D_N];       // [B,D] fp16 x (GEMM A)
__device__ float  g_counts[K_N];
__device__ float  g_enorm[K_N];
__device__ int    g_idx[B_N];
__device__ int    g_fall[B_N];
__device__ int    g_nfall;
__device__ float  g_scalars[4];          // 0: loss_sum, 1: n_sum, 2: n_small

// ---------------- fused pre-pass: zero + x->fp16 + transpose + enorm -------
// Block-range partitioned: independent jobs in ONE launch.
#define BD4 (B_N * D_N / 4)              // 4194304 float4s -> 16384 blocks
#define PRE_ZERO_BLKS 16384
#define PRE_TR_BLKS   1024               // 128 x 8 tiles of 32x32
#define PRE_EN_BLKS   16                 // 16 x 256 = 4096 codes
#define PRE_BLKS (PRE_ZERO_BLKS + PRE_TR_BLKS + PRE_EN_BLKS)

__global__ __launch_bounds__(256)
void k_pre(const float* __restrict__ x, const float* __restrict__ embed) {
    int bid = blockIdx.x;
    int tid = threadIdx.x;

    if (bid < PRE_ZERO_BLKS) {
        int i = bid * 256 + tid;
        // x -> fp16 convert
        float4 v = reinterpret_cast<const float4*>(x)[i];
        __half2* o = reinterpret_cast<__half2*>(g_xh) + i * 2;
        o[0] = __floats2half2_rn(v.x, v.y);
        o[1] = __floats2half2_rn(v.z, v.w);
        // zero scratch
        if (i < K_N * D_N / 4)
            reinterpret_cast<float4*>(g_sumT)[i] = make_float4(0.f, 0.f, 0.f, 0.f);
        if (i < K_N) g_counts[i] = 0.0f;
        if (i < 4) g_scalars[i] = 0.0f;
        if (i == 0) g_nfall = 0;
    } else if (bid < PRE_ZERO_BLKS + PRE_TR_BLKS) {
        // transpose embed [D,K] -> [K,D] (f32 + fp16)
        __shared__ float t[32][33];
        int b2 = bid - PRE_ZERO_BLKS;
        int bx = b2 & 127, by = b2 >> 7;
        int tx = tid & 31, ty = tid >> 5;         // 32 x 8
        int kx = bx * 32 + tx;
        int dy = by * 32 + ty;
        #pragma unroll
        for (int i = 0; i < 32; i += 8)
            t[ty + i][tx] = embed[(dy + i) * K_N + kx];
        __syncthreads();
        int k2 = bx * 32 + ty;
        int d2 = by * 32 + tx;
        #pragma unroll
        for (int i = 0; i < 32; i += 8) {
            float v = t[tx][ty + i];
            g_embedT[(k2 + i) * D_N + d2] = v;
            g_ebh[(k2 + i) * D_N + d2] = __float2half_rn(v);
        }
    } else {
        // ||e_k||^2 — identical per-thread sequential-d accumulation
        int k = (bid - PRE_ZERO_BLKS - PRE_TR_BLKS) * 256 + tid;
        float acc = 0.0f;
        #pragma unroll 16
        for (int d = 0; d < D_N; d++) {
            float v = embed[d * K_N + k];
            acc = fmaf(v, v, acc);
        }
        g_enorm[k] = acc;
    }
}

// ---------------- mma / ldmatrix / cp.async helpers ------------------------
__device__ __forceinline__ void mma_f16(float* c, const unsigned* a, const unsigned* b) {
    asm volatile(
        "mma.sync.aligned.m16n8k16.row.col.f32.f16.f16.f32 "
        "{%0,%1,%2,%3}, {%4,%5,%6,%7}, {%8,%9}, {%0,%1,%2,%3};\n"
        : "+f"(c[0]), "+f"(c[1]), "+f"(c[2]), "+f"(c[3])
        : "r"(a[0]), "r"(a[1]), "r"(a[2]), "r"(a[3]), "r"(b[0]), "r"(b[1]));
}
#define LDSM_X4(r0, r1, r2, r3, addr) \
    asm volatile("ldmatrix.sync.aligned.m8n8.x4.shared.b16 {%0,%1,%2,%3}, [%4];" \
        : "=r"(r0), "=r"(r1), "=r"(r2), "=r"(r3) : "r"(addr))
__device__ __forceinline__ void cp16(unsigned dst, const void* src) {
    asm volatile("cp.async.ca.shared.global [%0], [%1], 16;\n" :: "r"(dst), "l"(src));
}
__device__ __forceinline__ void cp_commit() { asm volatile("cp.async.commit_group;\n"); }
template <int N>
__device__ __forceinline__ void cp_wait() {
    asm volatile("cp.async.wait_group %0;\n" :: "n"(N));
}
__device__ __forceinline__ void red_add_v4(float* addr, float4 v) {
    asm volatile("red.global.v4.f32.add [%0], {%1, %2, %3, %4};"
                 :: "l"(addr), "f"(v.x), "f"(v.y), "f"(v.z), "f"(v.w) : "memory");
}

// ---------------- fused fp16 GEMM + in-kernel certification ----------------
#define GBM 128
#define GBN 128
#define AROWB 528               // (256 + 8 pad) halfs = 528 bytes per row
#define ABYTES (GBM * AROWB)    // 67584
#define BBYTES (GBN * AROWB)    // 67584
#define SMEM_GEMM (ABYTES + 2 * BBYTES)   // 202752
#define NT (K_N / GBN)          // 32

__global__ __launch_bounds__(512, 1)
void k_gemm_top2(const __half* __restrict__ xh, const __half* __restrict__ ebh) {
    extern __shared__ __align__(16) unsigned char raw[];
    __shared__ float sEn[K_N];            // full enorm table, written once
    __shared__ float sS1[GBM][4], sS2[GBM][4];
    __shared__ int   sK1[GBM][4], sK2[GBM][4];

    const int tid = threadIdx.x;
    const int m0 = blockIdx.x * GBM;
    const int warp = tid >> 5, lane = tid & 31;
    const int wm = warp >> 2, wn = warp & 3;   // 4x4 warp grid, warp tile 32x32
    const int g = lane >> 2, q = lane & 3;

    const unsigned sA = (unsigned)__cvta_generic_to_shared(raw);
    const unsigned sB0 = sA + ABYTES;

    for (int i = tid; i < K_N; i += 512) sEn[i] = g_enorm[i];

    const unsigned a_lane_off = (unsigned)((lane & 15) * AROWB + ((lane >> 4) << 4));
    const unsigned b_lane_off =
        (unsigned)(((lane & 7) + ((lane & 16) >> 1)) * AROWB + ((lane & 8) << 1));

    // ---- load A (whole 128 x 256 tile) once ----
    #pragma unroll
    for (int i = tid; i < GBM * 32; i += 512) {
        int r = i >> 5, c8 = i & 31;
        cp16(sA + r * AROWB + c8 * 16, xh + (m0 + r) * D_N + c8 * 8);
    }
    cp_commit();
    // ---- load B tile 0 ----
    #pragma unroll
    for (int i = tid; i < GBN * 32; i += 512) {
        int r = i >> 5, c8 = i & 31;
        cp16(sB0 + r * AROWB + c8 * 16, ebh + r * D_N + c8 * 8);
    }
    cp_commit();

    float t1s[4], t2s[4];
    unsigned pk[4];
    #pragma unroll
    for (int i = 0; i < 4; i++) { t1s[i] = 3.4e38f; t2s[i] = 3.4e38f; pk[i] = 0; }

    for (int t = 0; t < NT; t++) {
        const unsigned bb = sB0 + (t & 1) * BBYTES;
        if (t + 1 < NT) {
            const __half* src = ebh + (t + 1) * GBN * D_N;
            unsigned nb = sB0 + ((t + 1) & 1) * BBYTES;
            #pragma unroll
            for (int i = tid; i < GBN * 32; i += 512) {
                int r = i >> 5, c8 = i & 31;
                cp16(nb + r * AROWB + c8 * 16, src + r * D_N + c8 * 8);
            }
            cp_commit();
            cp_wait<1>();
        } else {
            cp_wait<0>();
        }
        __syncthreads();

        float acc[2][4][4];
        #pragma unroll
        for (int a = 0; a < 2; a++)
            #pragma unroll
            for (int b = 0; b < 4; b++)
                #pragma unroll
                for (int c = 0; c < 4; c++) acc[a][b][c] = 0.0f;

        #pragma unroll
        for (int k0 = 0; k0 < D_N; k0 += 16) {
            unsigned a[2][4], b[2][4];
            #pragma unroll
            for (int mf = 0; mf < 2; mf++) {
                unsigned addr = sA + (wm * 32 + mf * 16) * AROWB + a_lane_off + k0 * 2;
                LDSM_X4(a[mf][0], a[mf][1], a[mf][2], a[mf][3], addr);
            }
            #pragma unroll
            for (int pr = 0; pr < 2; pr++) {
                unsigned addr = bb + (wn * 32 + pr * 16) * AROWB + b_lane_off + k0 * 2;
                LDSM_X4(b[pr][0], b[pr][1], b[pr][2], b[pr][3], addr);
            }
            #pragma unroll
            for (int mf = 0; mf < 2; mf++)
                #pragma unroll
                for (int nf = 0; nf < 4; nf++)
                    mma_f16(acc[mf][nf], a[mf], &b[nf >> 1][(nf & 1) * 2]);
        }
        __syncthreads();

        const int n0 = t * GBN;
        #pragma unroll
        for (int nf = 0; nf < 4; nf++) {
            #pragma unroll
            for (int e = 0; e < 2; e++) {
                int col = wn * 32 + nf * 8 + 2 * q + e;
                int k = n0 + col;
                float en = sEn[k];
                #pragma unroll
                for (int mf = 0; mf < 2; mf++) {
                    #pragma unroll
                    for (int h = 0; h < 2; h++) {
                        float s = fmaf(-2.0f, acc[mf][nf][h * 2 + e], en);
                        int rid = mf * 2 + h;
                        if (s < t1s[rid]) {
                            t2s[rid] = t1s[rid];
                            t1s[rid] = s;
                            pk[rid] = ((pk[rid] & 0xffffu) << 16) | (unsigned)k;
                        } else if (s < t2s[rid]) {
                            t2s[rid] = s;
                            pk[rid] = (pk[rid] & 0xffffu) | ((unsigned)k << 16);
                        }
                    }
                }
            }
        }
    }

    // ---- in-warp merge of top-2 across the 4 q-lanes sharing each row ----
    #pragma unroll
    for (int rid = 0; rid < 4; rid++) {
        #pragma unroll
        for (int off = 1; off <= 2; off <<= 1) {
            float o1 = __shfl_xor_sync(0xffffffffu, t1s[rid], off);
            float o2 = __shfl_xor_sync(0xffffffffu, t2s[rid], off);
            unsigned op = __shfl_xor_sync(0xffffffffu, pk[rid], off);
            int ok1 = (int)(op & 0xffffu), ok2 = (int)(op >> 16);
            float s1 = t1s[rid], s2 = t2s[rid];
            int k1 = (int)(pk[rid] & 0xffffu), k2 = (int)(pk[rid] >> 16);
            float n1, n2; int nk1, nk2;
            bool ob = (o1 < s1) || (o1 == s1 && ok1 < k1);
            if (ob) {
                n1 = o1; nk1 = ok1;
                bool tb = (s1 < o2) || (s1 == o2 && k1 < ok2);
                if (tb) { n2 = s1; nk2 = k1; } else { n2 = o2; nk2 = ok2; }
            } else {
                n1 = s1; nk1 = k1;
                bool tb = (o1 < s2) || (o1 == s2 && ok1 < k2);
                if (tb) { n2 = o1; nk2 = ok1; } else { n2 = s2; nk2 = k2; }
            }
            t1s[rid] = n1; t2s[rid] = n2;
            pk[rid] = (unsigned)nk1 | ((unsigned)nk2 << 16);
        }
    }
    if (q == 0) {
        #pragma unroll
        for (int rid = 0; rid < 4; rid++) {
            int mf = rid >> 1, h = rid & 1;
            int rl = wm * 32 + mf * 16 + h * 8 + g;
            sS1[rl][wn] = t1s[rid]; sK1[rl][wn] = (int)(pk[rid] & 0xffffu);
            sS2[rl][wn] = t2s[rid]; sK2[rl][wn] = (int)(pk[rid] >> 16);
        }
    }
    __syncthreads();
    // ---- final cross-warp merge + certification (one thread per row) ----
    if (tid < GBM) {
        float b1 = 3.4e38f, b2 = 3.4e38f; int bk = 1 << 30;
        #pragma unroll
        for (int w = 0; w < 4; w++) {
            float s1 = sS1[tid][w]; int kk1 = sK1[tid][w];
            float s2 = sS2[tid][w]; int kk2 = sK2[tid][w];
            if (s1 < b1 || (s1 == b1 && kk1 < bk)) { b2 = b1; b1 = s1; bk = kk1; }
            else if (s1 < b2) b2 = s1;
            if (s2 < b1 || (s2 == b1 && kk2 < bk)) { b2 = b1; b1 = s2; bk = kk2; }
            else if (s2 < b2) b2 = s2;
        }
        int row = m0 + tid;
        g_idx[row] = bk;
        if (b2 - b1 < TAU) {
            int pos = atomicAdd(&g_nfall, 1);
            g_fall[pos] = row;
        }
    }
}

// ---------------- full exact scan for flagged rows -------------------------
__global__ __launch_bounds__(256)
void k_fallback(const float* __restrict__ x, const float* __restrict__ embed) {
    __shared__ float xs[D_N];
    __shared__ float rS[8];
    __shared__ int   rK[8];
    int tid = threadIdx.x, lane = tid & 31, warp = tid >> 5;
    int n = g_nfall;
    for (int w = blockIdx.x; w < n; w += gridDim.x) {
        int row = g_fall[w];
        __syncthreads();
        xs[tid] = x[row * D_N + tid];
        __syncthreads();

        float acc[16];
        #pragma unroll
        for (int j = 0; j < 16; j++) acc[j] = 0.0f;
        for (int d = 0; d < D_N; d++) {
            float xd = xs[d];
            const float* er = embed + d * K_N + tid;
            #pragma unroll
            for (int j = 0; j < 16; j++)
                acc[j] = fmaf(xd, er[j * 256], acc[j]);
        }
        float bs = 3.4e38f; int bk = 1 << 30;
        #pragma unroll
        for (int j = 0; j < 16; j++) {
            int k = tid + j * 256;
            float s = fmaf(-2.0f, acc[j], g_enorm[k]);
            if (s < bs || (s == bs && k < bk)) { bs = s; bk = k; }
        }
        #pragma unroll
        for (int o = 16; o > 0; o >>= 1) {
            float os = __shfl_down_sync(0xffffffffu, bs, o);
            int   ok = __shfl_down_sync(0xffffffffu, bk, o);
            if (os < bs || (os == bs && ok < bk)) { bs = os; bk = ok; }
        }
        if (lane == 0) { rS[warp] = bs; rK[warp] = bk; }
        __syncthreads();
        if (tid == 0) {
            float fbs = rS[0]; int fbk = rK[0];
            #pragma unroll
            for (int t = 1; t < 8; t++) {
                if (rS[t] < fbs || (rS[t] == fbs && rK[t] < fbk)) {
                    fbs = rS[t]; fbk = rK[t];
                }
            }
            g_idx[row] = fbk;
        }
    }
}

// ---------------- quantize + STE + loss + histogram + scatter-add ---------
// Two rows per warp; all 8 float4 loads issued up front for MLP.
__global__ __launch_bounds__(256)
void k_quant(const float* __restrict__ x, float* __restrict__ out) {
    __shared__ float blk_loss;
    if (threadIdx.x == 0) blk_loss = 0.0f;
    __syncthreads();

    int warp = threadIdx.x >> 5, lane = threadIdx.x & 31;
    int rowA = blockIdx.x * 16 + warp * 2;
    int rowB = rowA + 1;
    int kA = g_idx[rowA], kB = g_idx[rowB];

    const float4* xrA = reinterpret_cast<const float4*>(x + rowA * D_N);
    const float4* xrB = reinterpret_cast<const float4*>(x + rowB * D_N);
    const float4* erA = reinterpret_cast<const float4*>(g_embedT + kA * D_N);
    const float4* erB = reinterpret_cast<const float4*>(g_embedT + kB * D_N);
    int c0 = lane * 2, c1 = lane * 2 + 1;

    float4 xa0 = xrA[c0], xa1 = xrA[c1];
    float4 xb0 = xrB[c0], xb1 = xrB[c1];
    float4 ea0 = erA[c0], ea1 = erA[c1];
    float4 eb0 = erB[c0], eb1 = erB[c1];

    float4* outA = reinterpret_cast<float4*>(out + OFF_Q + rowA * D_N);
    float4* outB = reinterpret_cast<float4*>(out + OFF_Q + rowB * D_N);

    float lacc = 0.0f;
    {
        float d0 = ea0.x - xa0.x, d1 = ea0.y - xa0.y, d2 = ea0.z - xa0.z, d3 = ea0.w - xa0.w;
        outA[c0] = make_float4(xa0.x + d0, xa0.y + d1, xa0.z + d2, xa0.w + d3);
        lacc = fmaf(d0, d0, lacc); lacc = fmaf(d1, d1, lacc);
        lacc = fmaf(d2, d2, lacc); lacc = fmaf(d3, d3, lacc);
        red_add_v4(&g_sumT[kA * D_N + c0 * 4], xa0);
        float e0 = ea1.x - xa1.x, e1 = ea1.y - xa1.y, e2 = ea1.z - xa1.z, e3 = ea1.w - xa1.w;
        outA[c1] = make_float4(xa1.x + e0, xa1.y + e1, xa1.z + e2, xa1.w + e3);
        lacc = fmaf(e0, e0, lacc); lacc = fmaf(e1, e1, lacc);
        lacc = fmaf(e2, e2, lacc); lacc = fmaf(e3, e3, lacc);
        red_add_v4(&g_sumT[kA * D_N + c1 * 4], xa1);
    }
    {
        float d0 = eb0.x - xb0.x, d1 = eb0.y - xb0.y, d2 = eb0.z - xb0.z, d3 = eb0.w - xb0.w;
        outB[c0] = make_float4(xb0.x + d0, xb0.y + d1, xb0.z + d2, xb0.w + d3);
        lacc = fmaf(d0, d0, lacc); lacc = fmaf(d1, d1, lacc);
        lacc = fmaf(d2, d2, lacc); lacc = fmaf(d3, d3, lacc);
        red_add_v4(&g_sumT[kB * D_N + c0 * 4], xb0);
        float e0 = eb1.x - xb1.x, e1 = eb1.y - xb1.y, e2 = eb1.z - xb1.z, e3 = eb1.w - xb1.w;
        outB[c1] = make_float4(xb1.x + e0, xb1.y + e1, xb1.z + e2, xb1.w + e3);
        lacc = fmaf(e0, e0, lacc); lacc = fmaf(e1, e1, lacc);
        lacc = fmaf(e2, e2, lacc); lacc = fmaf(e3, e3, lacc);
        red_add_v4(&g_sumT[kB * D_N + c1 * 4], xb1);
    }

    #pragma unroll
    for (int o = 16; o > 0; o >>= 1) lacc += __shfl_down_sync(0xffffffffu, lacc, o);
    if (lane == 0) {
        atomicAdd(&blk_loss, lacc);
        atomicAdd(&g_counts[kA], 1.0f);
        atomicAdd(&g_counts[kB], 1.0f);
        out[OFF_IDX + rowA] = (float)kA;
        out[OFF_IDX + rowB] = (float)kB;
    }
    __syncthreads();
    if (threadIdx.x == 0) atomicAdd(&g_scalars[0], blk_loss);
}

// ---------------- new_cluster_size + reductions ---------------------------
__global__ void k_stats(const float* __restrict__ cluster_size,
                        float* __restrict__ out) {
    __shared__ float sSum[256], sSmall[256];
    int tid = threadIdx.x;
    int k = blockIdx.x * 256 + tid;
    float ncs = fmaf(DECAYF, cluster_size[k], OMDECAYF * g_counts[k]);
    out[OFF_CS + k] = ncs;
    sSum[tid] = ncs;
    sSmall[tid] = (ncs < 1.0f) ? 1.0f : 0.0f;
    __syncthreads();
    for (int o = 128; o > 0; o >>= 1) {
        if (tid < o) { sSum[tid] += sSum[tid + o]; sSmall[tid] += sSmall[tid + o]; }
        __syncthreads();
    }
    if (tid == 0) {
        atomicAdd(&g_scalars[1], sSum[0]);
        atomicAdd(&g_scalars[2], sSmall[0]);
    }
}

// ---------------- finalize: new_embed + scalars ---------------------------
__global__ void k_final(const float* __restrict__ embed_avg,
                        float* __restrict__ out) {
    int i = blockIdx.x * blockDim.x + threadIdx.x;
    if (i == 0) {
        out[OFF_NS]   = g_scalars[2];
        out[OFF_LOSS] = g_scalars[0] * (1.0f / ((float)B_N * (float)D_N));
    }
    if (i < D_N * K_N) {
        int k = i & (K_N - 1);
        int d = i >> 12;
        float ncs = out[OFF_CS + k];
        float n = g_scalars[1];
        float cs = (ncs + EPSF) / (n + (float)K_N * EPSF) * n;
        float navg = fmaf(DECAYF, embed_avg[i], OMDECAYF * g_sumT[k * D_N + d]);
        out[OFF_E + i] = navg / cs;
    }
}

// ---------------- launch ---------------------------------------------------
extern "C" void kernel_launch(void* const* d_in, const int* in_sizes, int n_in,
                              void* d_out, int out_size) {
    const float* x            = (const float*)d_in[0];  // [B, D]
    const float* embed        = (const float*)d_in[1];  // [D, K]
    const float* cluster_size = (const float*)d_in[2];  // [K]
    const float* embed_avg    = (const float*)d_in[3];  // [D, K]
    float* out = (float*)d_out;
    (void)in_sizes; (void)n_in; (void)out_size;

    static int smem_set = 0;
    if (!smem_set) {
        cudaFuncSetAttribute(k_gemm_top2,
                             cudaFuncAttributeMaxDynamicSharedMemorySize, SMEM_GEMM);
        smem_set = 1;
    }

    __half* xh;  cudaGetSymbolAddress((void**)&xh, g_xh);
    __half* ebh; cudaGetSymbolAddress((void**)&ebh, g_ebh);

    k_pre<<<PRE_BLKS, 256>>>(x, embed);
    k_gemm_top2<<<B_N / GBM, 512, SMEM_GEMM>>>(xh, ebh);
    k_fallback<<<1024, 256>>>(x, embed);
    k_quant<<<B_N / 16, 256>>>(x, out);
    k_stats<<<K_N / 256, 256>>>(cluster_size, out);
    k_final<<<(D_N * K_N + 255) / 256, 256>>>(embed_avg, out);
}